// round 15
// baseline (speedup 1.0000x reference)
#include <cuda_runtime.h>
#include <cuda_fp16.h>
#include <cstdint>

#define NROWS 8192
#define D_IN  64
#define D_OUT 32000
#define MT 128
#define NT 128
#define NBLK   (D_OUT / NT)     // 250
#define NBLK2  (NBLK * 2)       // 500 partials per row
#define MBLK   (NROWS / MT)     // 64

// smem rows: 32 words fp16 + 4 pad = 36 words (144B) -> all ldmatrix phases
// bank-conflict-free.
#define PITCH 36
#define LOG2E 1.4426950408889634f

// -------------------- device scratch --------------------
__device__ uint32_t g_wprep[D_OUT * 32];   // [n][32] f16x2 of W^T * log2e
__device__ uint32_t g_xprep[NROWS * 32];   // [row][32] f16x2 of 1/x
__device__ float    g_partials[NROWS * NBLK2];
__device__ float    g_rowinv[NROWS];

__device__ __forceinline__ uint32_t pack_h2(float a, float b) {
    uint32_t lo = __half_as_ushort(__float2half_rn(a));
    uint32_t hi = __half_as_ushort(__float2half_rn(b));
    return lo | (hi << 16);
}
__device__ __forceinline__ uint32_t smem_u32(const void* p) {
    uint32_t a;
    asm("{ .reg .u64 t; cvta.to.shared.u64 t, %1; cvt.u32.u64 %0, t; }" : "=r"(a) : "l"(p));
    return a;
}
__device__ __forceinline__ void cpa16(uint32_t s, const void* g) {
    asm volatile("cp.async.cg.shared.global [%0], [%1], 16;" :: "r"(s), "l"(g));
}
__device__ __forceinline__ void ldsm4(uint32_t* r, uint32_t a) {
    asm volatile("ldmatrix.sync.aligned.m8n8.x4.shared.b16 {%0,%1,%2,%3}, [%4];"
                 : "=r"(r[0]), "=r"(r[1]), "=r"(r[2]), "=r"(r[3]) : "r"(a));
}
__device__ __forceinline__ void mma_f16(float* c, const uint32_t* a, uint32_t b0, uint32_t b1) {
    asm volatile(
        "mma.sync.aligned.m16n8k16.row.col.f32.f16.f16.f32 "
        "{%0,%1,%2,%3}, {%4,%5,%6,%7}, {%8,%9}, {%0,%1,%2,%3};"
        : "+f"(c[0]), "+f"(c[1]), "+f"(c[2]), "+f"(c[3])
        : "r"(a[0]), "r"(a[1]), "r"(a[2]), "r"(a[3]), "r"(b0), "r"(b1));
}
__device__ __forceinline__ float ex2(float x) {
    float y;
    asm("ex2.approx.f32 %0, %1;" : "=f"(y) : "f"(x));
    return y;
}
// pack two fp32 -> fp16x2, 2-wide exp2, unpack to two fp32
__device__ __forceinline__ float2 ex2_pair(float a, float b) {
    uint32_t p, e;
    asm("cvt.rn.f16x2.f32 %0, %1, %2;" : "=r"(p) : "f"(b), "f"(a));
    asm("ex2.approx.f16x2 %0, %1;" : "=r"(e) : "r"(p));
    __half2 h = *reinterpret_cast<__half2*>(&e);
    return __half22float2(h);
}

// ---------------------------------------------------------------------------
// prep: blocks [0,125) convert W (n = blk*256+tid), blocks [125,189) convert x.
// ---------------------------------------------------------------------------
__global__ __launch_bounds__(256) void prep_kernel(const float* __restrict__ w,
                                                   const float* __restrict__ x) {
    if (blockIdx.x < 125) {
        int n = blockIdx.x * 256 + threadIdx.x;
        uint32_t hi[32];
#pragma unroll
        for (int j = 0; j < 32; ++j) {
            float v0 = w[(2 * j) * D_OUT + n] * LOG2E;
            float v1 = w[(2 * j + 1) * D_OUT + n] * LOG2E;
            hi[j] = pack_h2(v0, v1);
        }
        uint4* d = reinterpret_cast<uint4*>(g_wprep) + (size_t)n * 8;
#pragma unroll
        for (int j = 0; j < 8; ++j)
            d[j] = make_uint4(hi[4*j], hi[4*j+1], hi[4*j+2], hi[4*j+3]);
    } else {
        int tid = (blockIdx.x - 125) * 256 + threadIdx.x;
        int row = tid >> 1, half = tid & 1;
        const float4* xr = reinterpret_cast<const float4*>(&x[(size_t)row * D_IN + half * 32]);
        uint32_t hi[16];
#pragma unroll
        for (int j = 0; j < 8; ++j) {
            float4 v = xr[j];
            hi[2*j]   = pack_h2(1.0f / v.x, 1.0f / v.y);
            hi[2*j+1] = pack_h2(1.0f / v.z, 1.0f / v.w);
        }
        uint4* d = reinterpret_cast<uint4*>(g_xprep) + (size_t)row * 8 + half * 4;
#pragma unroll
        for (int j = 0; j < 4; ++j)
            d[j] = make_uint4(hi[4*j], hi[4*j+1], hi[4*j+2], hi[4*j+3]);
    }
}

// ---------------------------------------------------------------------------
// Main HMMA pass. do_store=0: exp-sums into g_partials (fp16x2 ex2 path).
//                 do_store=1: out = 2^logit2 * rowinv (fp32 ex2).
// ---------------------------------------------------------------------------
__global__ __launch_bounds__(256, 2)
void mma_pass_kernel(float* __restrict__ out, int do_store) {
    extern __shared__ uint32_t smem[];
    uint32_t* sA = smem;                 // [128][36]
    uint32_t* sB = smem + 128 * PITCH;   // [128][36]

    const int tid  = threadIdx.x;
    const int wid  = tid >> 5;
    const int lane = tid & 31;
    const int m0 = blockIdx.y * MT;
    const int n0 = blockIdx.x * NT;

    const uint32_t sA_a = smem_u32(sA);
    const uint32_t sB_a = smem_u32(sB);

    // ---- prologue: cp.async of prepped tiles (each 1024 uint4, 4/thread) ----
    {
        const uint4* gA = reinterpret_cast<const uint4*>(g_xprep + (size_t)m0 * 32);
        const uint4* gB = reinterpret_cast<const uint4*>(g_wprep + (size_t)n0 * 32);
#pragma unroll
        for (int j = 0; j < 4; ++j) {
            int f = tid + 256 * j;                               // 0..1023
            uint32_t doff = ((f >> 3) * PITCH + (f & 7) * 4) * 4;
            cpa16(sA_a + doff, gA + f);
            cpa16(sB_a + doff, gB + f);
        }
        asm volatile("cp.async.commit_group;" ::: "memory");
        asm volatile("cp.async.wait_group 0;" ::: "memory");
    }
    __syncthreads();

    // ---- fragment base addresses ----
    const int wm = wid & 3;
    const int wn = wid >> 2;
    const int g  = lane >> 2;
    const int t  = lane & 3;

    uint32_t aBase[2];
    {
        int arow = lane & 15;
        int ako  = (lane >> 4) * 16;
#pragma unroll
        for (int mi = 0; mi < 2; ++mi)
            aBase[mi] = sA_a + (uint32_t)(wm * 32 + mi * 16 + arow) * (PITCH * 4u) + ako;
    }
    uint32_t bBase[4];
    {
        int brow  = (lane & 7) + ((lane >> 4) & 1) * 8;
        int bko   = ((lane >> 3) & 1) * 16;
        uint32_t laneoff = (uint32_t)brow * (PITCH * 4u) + bko;
#pragma unroll
        for (int np = 0; np < 4; ++np)
            bBase[np] = sB_a + (uint32_t)(wn * 64 + np * 16) * (PITCH * 4u) + laneoff;
    }

    float acc[2][8][4];
#pragma unroll
    for (int mi = 0; mi < 2; ++mi)
#pragma unroll
        for (int ni = 0; ni < 8; ++ni)
#pragma unroll
            for (int c = 0; c < 4; ++c) acc[mi][ni][c] = 0.0f;

    // ---- mainloop: 4 k-chunks x (2 A-LDSM + 4 B-LDSM + 16 HMMA) ----
#pragma unroll
    for (int kc = 0; kc < 4; ++kc) {
        const uint32_t ko = kc * 32u;
        uint32_t ah[2][4];
#pragma unroll
        for (int mi = 0; mi < 2; ++mi)
            ldsm4(ah[mi], aBase[mi] + ko);
#pragma unroll
        for (int np = 0; np < 4; ++np) {
            uint32_t b[4];
            ldsm4(b, bBase[np] + ko);
#pragma unroll
            for (int mi = 0; mi < 2; ++mi) {
                mma_f16(acc[mi][2*np],     ah[mi], b[0], b[1]);
                mma_f16(acc[mi][2*np + 1], ah[mi], b[2], b[3]);
            }
        }
    }

    // ---- epilogue ----
#pragma unroll
    for (int mi = 0; mi < 2; ++mi) {
        const int rg = m0 + wm * 32 + mi * 16 + g;
        if (do_store) {
            const float inv0 = g_rowinv[rg];
            const float inv8 = g_rowinv[rg + 8];
            float* r0p = out + (size_t)rg * D_OUT + n0 + wn * 64 + t * 2;
            float* r8p = r0p + (size_t)8 * D_OUT;
#pragma unroll
            for (int ni = 0; ni < 8; ++ni) {
                float e0 = ex2(acc[mi][ni][0]);
                float e1 = ex2(acc[mi][ni][1]);
                float e2 = ex2(acc[mi][ni][2]);
                float e3 = ex2(acc[mi][ni][3]);
                __stcs(reinterpret_cast<float2*>(r0p + ni * 8), make_float2(e0 * inv0, e1 * inv0));
                __stcs(reinterpret_cast<float2*>(r8p + ni * 8), make_float2(e2 * inv8, e3 * inv8));
            }
        } else {
            float s0 = 0.0f, s8 = 0.0f;
#pragma unroll
            for (int ni = 0; ni < 8; ++ni) {
                float2 f01 = ex2_pair(acc[mi][ni][0], acc[mi][ni][1]);
                float2 f23 = ex2_pair(acc[mi][ni][2], acc[mi][ni][3]);
                s0 += f01.x + f01.y;
                s8 += f23.x + f23.y;
            }
            s0 += __shfl_xor_sync(0xffffffffu, s0, 1);
            s0 += __shfl_xor_sync(0xffffffffu, s0, 2);
            s8 += __shfl_xor_sync(0xffffffffu, s8, 1);
            s8 += __shfl_xor_sync(0xffffffffu, s8, 2);
            if (t == 0) {
                int pcol = blockIdx.x * 2 + wn;
                __stcs(&g_partials[(size_t)rg * NBLK2 + pcol], s0);
                __stcs(&g_partials[(size_t)(rg + 8) * NBLK2 + pcol], s8);
            }
        }
    }
}

// ---------------------------------------------------------------------------
__global__ __launch_bounds__(256) void rowinv_kernel() {
    int warp = threadIdx.x >> 5;
    int lane = threadIdx.x & 31;
    int row = blockIdx.x * 8 + warp;
    float s = 0.0f;
    for (int i = lane; i < NBLK2; i += 32) s += g_partials[(size_t)row * NBLK2 + i];
#pragma unroll
    for (int off = 16; off >= 1; off >>= 1)
        s += __shfl_xor_sync(0xffffffffu, s, off);
    if (lane == 0) g_rowinv[row] = 1.0f / s;
}

__global__ void tail_kernel(float* __restrict__ out, long long base, long long n) {
    long long i = (long long)blockIdx.x * 256 + threadIdx.x;
    if (i < n) out[base + i] = 0.0f;
}

extern "C" void kernel_launch(void* const* d_in, const int* in_sizes, int n_in,
                              void* d_out, int out_size) {
    const float* x = (const float*)d_in[0];
    const float* w = (const float*)d_in[1];
    float* out = (float*)d_out;

    const int smem_bytes = 2 * 128 * PITCH * 4;   // 36864
    static int attr_set = 0;
    if (!attr_set) {
        cudaFuncSetAttribute(mma_pass_kernel,
                             cudaFuncAttributeMaxDynamicSharedMemorySize, smem_bytes);
        attr_set = 1;
    }

    prep_kernel<<<189, 256>>>(w, x);   // 125 W-blocks + 64 x-blocks

    dim3 grid(NBLK, MBLK);   // (250, 64)
    mma_pass_kernel<<<grid, 256, smem_bytes>>>(out, 0);
    rowinv_kernel<<<NROWS / 8, 256>>>();
    mma_pass_kernel<<<grid, 256, smem_bytes>>>(out, 1);

    long long n_main = (long long)NROWS * D_OUT;
    long long tail = (long long)out_size - n_main;
    if (tail > 0) {
        int blocks = (int)((tail + 255) / 256);
        tail_kernel<<<blocks, 256>>>(out, n_main, tail);
    }
}

// round 16
// speedup vs baseline: 1.0001x; 1.0001x over previous
#include <cuda_runtime.h>
#include <cuda_fp16.h>
#include <cstdint>

#define NROWS 8192
#define D_IN  64
#define D_OUT 32000
#define MT 128
#define NT 128
#define NBLK   (D_OUT / NT)     // 250
#define NBLK2  (NBLK * 2)       // 500 partials per row
#define MBLK   (NROWS / MT)     // 64

// smem rows: 32 words fp16 + 4 pad = 36 words (144B) -> all ldmatrix phases
// bank-conflict-free.
#define PITCH 36
#define LOG2E 1.4426950408889634f

// -------------------- device scratch --------------------
__device__ uint32_t g_wprep[D_OUT * 32];   // [n][32] f16x2 of W^T * log2e
__device__ uint32_t g_xprep[NROWS * 32];   // [row][32] f16x2 of 1/x
__device__ float    g_partials[NROWS * NBLK2];
__device__ float    g_rowinv[NROWS];

__device__ __forceinline__ uint32_t pack_h2(float a, float b) {
    uint32_t lo = __half_as_ushort(__float2half_rn(a));
    uint32_t hi = __half_as_ushort(__float2half_rn(b));
    return lo | (hi << 16);
}
__device__ __forceinline__ uint32_t smem_u32(const void* p) {
    uint32_t a;
    asm("{ .reg .u64 t; cvta.to.shared.u64 t, %1; cvt.u32.u64 %0, t; }" : "=r"(a) : "l"(p));
    return a;
}
__device__ __forceinline__ void cpa16(uint32_t s, const void* g) {
    asm volatile("cp.async.cg.shared.global [%0], [%1], 16;" :: "r"(s), "l"(g));
}
__device__ __forceinline__ void ldsm4(uint32_t* r, uint32_t a) {
    asm volatile("ldmatrix.sync.aligned.m8n8.x4.shared.b16 {%0,%1,%2,%3}, [%4];"
                 : "=r"(r[0]), "=r"(r[1]), "=r"(r[2]), "=r"(r[3]) : "r"(a));
}
__device__ __forceinline__ void mma_f16(float* c, const uint32_t* a, uint32_t b0, uint32_t b1) {
    asm volatile(
        "mma.sync.aligned.m16n8k16.row.col.f32.f16.f16.f32 "
        "{%0,%1,%2,%3}, {%4,%5,%6,%7}, {%8,%9}, {%0,%1,%2,%3};"
        : "+f"(c[0]), "+f"(c[1]), "+f"(c[2]), "+f"(c[3])
        : "r"(a[0]), "r"(a[1]), "r"(a[2]), "r"(a[3]), "r"(b0), "r"(b1));
}
__device__ __forceinline__ float ex2(float x) {
    float y;
    asm("ex2.approx.f32 %0, %1;" : "=f"(y) : "f"(x));
    return y;
}
// pack two fp32 -> fp16x2, 2-wide exp2, unpack to two fp32
__device__ __forceinline__ float2 ex2_pair(float a, float b) {
    uint32_t p, e;
    asm("cvt.rn.f16x2.f32 %0, %1, %2;" : "=r"(p) : "f"(b), "f"(a));
    asm("ex2.approx.f16x2 %0, %1;" : "=r"(e) : "r"(p));
    __half2 h = *reinterpret_cast<__half2*>(&e);
    return __half22float2(h);
}

// ---------------------------------------------------------------------------
// prep: blocks [0,125) convert W (n = blk*256+tid), blocks [125,189) convert x.
// ---------------------------------------------------------------------------
__global__ __launch_bounds__(256) void prep_kernel(const float* __restrict__ w,
                                                   const float* __restrict__ x) {
    if (blockIdx.x < 125) {
        int n = blockIdx.x * 256 + threadIdx.x;
        uint32_t hi[32];
#pragma unroll
        for (int j = 0; j < 32; ++j) {
            float v0 = w[(2 * j) * D_OUT + n] * LOG2E;
            float v1 = w[(2 * j + 1) * D_OUT + n] * LOG2E;
            hi[j] = pack_h2(v0, v1);
        }
        uint4* d = reinterpret_cast<uint4*>(g_wprep) + (size_t)n * 8;
#pragma unroll
        for (int j = 0; j < 8; ++j)
            d[j] = make_uint4(hi[4*j], hi[4*j+1], hi[4*j+2], hi[4*j+3]);
    } else {
        int tid = (blockIdx.x - 125) * 256 + threadIdx.x;
        int row = tid >> 1, half = tid & 1;
        const float4* xr = reinterpret_cast<const float4*>(&x[(size_t)row * D_IN + half * 32]);
        uint32_t hi[16];
#pragma unroll
        for (int j = 0; j < 8; ++j) {
            float4 v = xr[j];
            hi[2*j]   = pack_h2(1.0f / v.x, 1.0f / v.y);
            hi[2*j+1] = pack_h2(1.0f / v.z, 1.0f / v.w);
        }
        uint4* d = reinterpret_cast<uint4*>(g_xprep) + (size_t)row * 8 + half * 4;
#pragma unroll
        for (int j = 0; j < 4; ++j)
            d[j] = make_uint4(hi[4*j], hi[4*j+1], hi[4*j+2], hi[4*j+3]);
    }
}

// ---------------------------------------------------------------------------
// Main HMMA pass. do_store=0: exp-sums into g_partials (fp16x2 ex2 path).
//                 do_store=1: out = 2^logit2 * rowinv (fp32 ex2).
// ---------------------------------------------------------------------------
__global__ __launch_bounds__(256, 2)
void mma_pass_kernel(float* __restrict__ out, int do_store) {
    extern __shared__ uint32_t smem[];
    uint32_t* sA = smem;                 // [128][36]
    uint32_t* sB = smem + 128 * PITCH;   // [128][36]

    const int tid  = threadIdx.x;
    const int wid  = tid >> 5;
    const int lane = tid & 31;
    const int m0 = blockIdx.y * MT;
    const int n0 = blockIdx.x * NT;

    const uint32_t sA_a = smem_u32(sA);
    const uint32_t sB_a = smem_u32(sB);

    // ---- prologue: cp.async of prepped tiles (each 1024 uint4, 4/thread) ----
    {
        const uint4* gA = reinterpret_cast<const uint4*>(g_xprep + (size_t)m0 * 32);
        const uint4* gB = reinterpret_cast<const uint4*>(g_wprep + (size_t)n0 * 32);
#pragma unroll
        for (int j = 0; j < 4; ++j) {
            int f = tid + 256 * j;                               // 0..1023
            uint32_t doff = ((f >> 3) * PITCH + (f & 7) * 4) * 4;
            cpa16(sA_a + doff, gA + f);
            cpa16(sB_a + doff, gB + f);
        }
        asm volatile("cp.async.commit_group;" ::: "memory");
        asm volatile("cp.async.wait_group 0;" ::: "memory");
    }
    __syncthreads();

    // ---- fragment base addresses ----
    const int wm = wid & 3;
    const int wn = wid >> 2;
    const int g  = lane >> 2;
    const int t  = lane & 3;

    uint32_t aBase[2];
    {
        int arow = lane & 15;
        int ako  = (lane >> 4) * 16;
#pragma unroll
        for (int mi = 0; mi < 2; ++mi)
            aBase[mi] = sA_a + (uint32_t)(wm * 32 + mi * 16 + arow) * (PITCH * 4u) + ako;
    }
    uint32_t bBase[4];
    {
        int brow  = (lane & 7) + ((lane >> 4) & 1) * 8;
        int bko   = ((lane >> 3) & 1) * 16;
        uint32_t laneoff = (uint32_t)brow * (PITCH * 4u) + bko;
#pragma unroll
        for (int np = 0; np < 4; ++np)
            bBase[np] = sB_a + (uint32_t)(wn * 64 + np * 16) * (PITCH * 4u) + laneoff;
    }

    float acc[2][8][4];
#pragma unroll
    for (int mi = 0; mi < 2; ++mi)
#pragma unroll
        for (int ni = 0; ni < 8; ++ni)
#pragma unroll
            for (int c = 0; c < 4; ++c) acc[mi][ni][c] = 0.0f;

    // ---- mainloop: 4 k-chunks x (2 A-LDSM + 4 B-LDSM + 16 HMMA) ----
#pragma unroll
    for (int kc = 0; kc < 4; ++kc) {
        const uint32_t ko = kc * 32u;
        uint32_t ah[2][4];
#pragma unroll
        for (int mi = 0; mi < 2; ++mi)
            ldsm4(ah[mi], aBase[mi] + ko);
#pragma unroll
        for (int np = 0; np < 4; ++np) {
            uint32_t b[4];
            ldsm4(b, bBase[np] + ko);
#pragma unroll
            for (int mi = 0; mi < 2; ++mi) {
                mma_f16(acc[mi][2*np],     ah[mi], b[0], b[1]);
                mma_f16(acc[mi][2*np + 1], ah[mi], b[2], b[3]);
            }
        }
    }

    // ---- epilogue ----
#pragma unroll
    for (int mi = 0; mi < 2; ++mi) {
        const int rg = m0 + wm * 32 + mi * 16 + g;
        if (do_store) {
            const float inv0 = g_rowinv[rg];
            const float inv8 = g_rowinv[rg + 8];
            float* r0p = out + (size_t)rg * D_OUT + n0 + wn * 64 + t * 2;
            float* r8p = r0p + (size_t)8 * D_OUT;
#pragma unroll
            for (int ni = 0; ni < 8; ++ni) {
                float e0 = ex2(acc[mi][ni][0]);
                float e1 = ex2(acc[mi][ni][1]);
                float e2 = ex2(acc[mi][ni][2]);
                float e3 = ex2(acc[mi][ni][3]);
                __stcs(reinterpret_cast<float2*>(r0p + ni * 8), make_float2(e0 * inv0, e1 * inv0));
                __stcs(reinterpret_cast<float2*>(r8p + ni * 8), make_float2(e2 * inv8, e3 * inv8));
            }
        } else {
            float s0 = 0.0f, s8 = 0.0f;
#pragma unroll
            for (int ni = 0; ni < 8; ++ni) {
                float2 f01 = ex2_pair(acc[mi][ni][0], acc[mi][ni][1]);
                float2 f23 = ex2_pair(acc[mi][ni][2], acc[mi][ni][3]);
                s0 += f01.x + f01.y;
                s8 += f23.x + f23.y;
            }
            s0 += __shfl_xor_sync(0xffffffffu, s0, 1);
            s0 += __shfl_xor_sync(0xffffffffu, s0, 2);
            s8 += __shfl_xor_sync(0xffffffffu, s8, 1);
            s8 += __shfl_xor_sync(0xffffffffu, s8, 2);
            if (t == 0) {
                int pcol = blockIdx.x * 2 + wn;
                __stcs(&g_partials[(size_t)rg * NBLK2 + pcol], s0);
                __stcs(&g_partials[(size_t)(rg + 8) * NBLK2 + pcol], s8);
            }
        }
    }
}

// ---------------------------------------------------------------------------
__global__ __launch_bounds__(256) void rowinv_kernel() {
    int warp = threadIdx.x >> 5;
    int lane = threadIdx.x & 31;
    int row = blockIdx.x * 8 + warp;
    float s = 0.0f;
    for (int i = lane; i < NBLK2; i += 32) s += g_partials[(size_t)row * NBLK2 + i];
#pragma unroll
    for (int off = 16; off >= 1; off >>= 1)
        s += __shfl_xor_sync(0xffffffffu, s, off);
    if (lane == 0) g_rowinv[row] = 1.0f / s;
}

__global__ void tail_kernel(float* __restrict__ out, long long base, long long n) {
    long long i = (long long)blockIdx.x * 256 + threadIdx.x;
    if (i < n) out[base + i] = 0.0f;
}

extern "C" void kernel_launch(void* const* d_in, const int* in_sizes, int n_in,
                              void* d_out, int out_size) {
    const float* x = (const float*)d_in[0];
    const float* w = (const float*)d_in[1];
    float* out = (float*)d_out;

    const int smem_bytes = 2 * 128 * PITCH * 4;   // 36864
    static int attr_set = 0;
    if (!attr_set) {
        cudaFuncSetAttribute(mma_pass_kernel,
                             cudaFuncAttributeMaxDynamicSharedMemorySize, smem_bytes);
        attr_set = 1;
    }

    prep_kernel<<<189, 256>>>(w, x);   // 125 W-blocks + 64 x-blocks

    dim3 grid(NBLK, MBLK);   // (250, 64)
    mma_pass_kernel<<<grid, 256, smem_bytes>>>(out, 0);
    rowinv_kernel<<<NROWS / 8, 256>>>();
    mma_pass_kernel<<<grid, 256, smem_bytes>>>(out, 1);

    long long n_main = (long long)NROWS * D_OUT;
    long long tail = (long long)out_size - n_main;
    if (tail > 0) {
        int blocks = (int)((tail + 255) / 256);
        tail_kernel<<<blocks, 256>>>(out, n_main, tail);
    }
}

// round 17
// speedup vs baseline: 1.0416x; 1.0415x over previous
#include <cuda_runtime.h>
#include <cuda_fp16.h>
#include <cstdint>

#define NROWS 8192
#define D_IN  64
#define D_OUT 32000
#define MT 128
#define NT 128
#define NBLK   (D_OUT / NT)     // 250
#define NBLK2  (NBLK * 2)       // 500 partials per row
#define MBLK   (NROWS / MT)     // 64
#define NBG    10               // n-blocks per CTA
#define NGX    (NBLK / NBG)     // 25

// smem rows: 32 words fp16 + 4 pad = 36 words (144B) -> all ldmatrix phases
// bank-conflict-free. Layout: [A tile][B buf0][B buf1]
#define PITCH 36
#define TILE_BYTES (128 * PITCH * 4)    // 18432
#define LOG2E 1.4426950408889634f

// -------------------- device scratch --------------------
__device__ uint32_t g_wprep[D_OUT * 32];   // [n][32] f16x2 of W^T * log2e
__device__ uint32_t g_xprep[NROWS * 32];   // [row][32] f16x2 of 1/x
__device__ float    g_partials[NROWS * NBLK2];
__device__ float    g_rowinv[NROWS];

__device__ __forceinline__ uint32_t pack_h2(float a, float b) {
    uint32_t lo = __half_as_ushort(__float2half_rn(a));
    uint32_t hi = __half_as_ushort(__float2half_rn(b));
    return lo | (hi << 16);
}
__device__ __forceinline__ uint32_t smem_u32(const void* p) {
    uint32_t a;
    asm("{ .reg .u64 t; cvta.to.shared.u64 t, %1; cvt.u32.u64 %0, t; }" : "=r"(a) : "l"(p));
    return a;
}
__device__ __forceinline__ void cpa16(uint32_t s, const void* g) {
    asm volatile("cp.async.cg.shared.global [%0], [%1], 16;" :: "r"(s), "l"(g));
}
__device__ __forceinline__ void ldsm4(uint32_t* r, uint32_t a) {
    asm volatile("ldmatrix.sync.aligned.m8n8.x4.shared.b16 {%0,%1,%2,%3}, [%4];"
                 : "=r"(r[0]), "=r"(r[1]), "=r"(r[2]), "=r"(r[3]) : "r"(a));
}
__device__ __forceinline__ void mma_f16(float* c, const uint32_t* a, uint32_t b0, uint32_t b1) {
    asm volatile(
        "mma.sync.aligned.m16n8k16.row.col.f32.f16.f16.f32 "
        "{%0,%1,%2,%3}, {%4,%5,%6,%7}, {%8,%9}, {%0,%1,%2,%3};"
        : "+f"(c[0]), "+f"(c[1]), "+f"(c[2]), "+f"(c[3])
        : "r"(a[0]), "r"(a[1]), "r"(a[2]), "r"(a[3]), "r"(b0), "r"(b1));
}
__device__ __forceinline__ float ex2(float x) {
    float y;
    asm("ex2.approx.f32 %0, %1;" : "=f"(y) : "f"(x));
    return y;
}
__device__ __forceinline__ float2 ex2_pair(float a, float b) {
    uint32_t p, e;
    asm("cvt.rn.f16x2.f32 %0, %1, %2;" : "=r"(p) : "f"(b), "f"(a));
    asm("ex2.approx.f16x2 %0, %1;" : "=r"(e) : "r"(p));
    __half2 h = *reinterpret_cast<__half2*>(&e);
    return __half22float2(h);
}

// ---------------------------------------------------------------------------
// prep: blocks [0,125) convert W, blocks [125,189) convert x.
// ---------------------------------------------------------------------------
__global__ __launch_bounds__(256) void prep_kernel(const float* __restrict__ w,
                                                   const float* __restrict__ x) {
    if (blockIdx.x < 125) {
        int n = blockIdx.x * 256 + threadIdx.x;
        uint32_t hi[32];
#pragma unroll
        for (int j = 0; j < 32; ++j) {
            float v0 = w[(2 * j) * D_OUT + n] * LOG2E;
            float v1 = w[(2 * j + 1) * D_OUT + n] * LOG2E;
            hi[j] = pack_h2(v0, v1);
        }
        uint4* d = reinterpret_cast<uint4*>(g_wprep) + (size_t)n * 8;
#pragma unroll
        for (int j = 0; j < 8; ++j)
            d[j] = make_uint4(hi[4*j], hi[4*j+1], hi[4*j+2], hi[4*j+3]);
    } else {
        int tid = (blockIdx.x - 125) * 256 + threadIdx.x;
        int row = tid >> 1, half = tid & 1;
        const float4* xr = reinterpret_cast<const float4*>(&x[(size_t)row * D_IN + half * 32]);
        uint32_t hi[16];
#pragma unroll
        for (int j = 0; j < 8; ++j) {
            float4 v = xr[j];
            hi[2*j]   = pack_h2(1.0f / v.x, 1.0f / v.y);
            hi[2*j+1] = pack_h2(1.0f / v.z, 1.0f / v.w);
        }
        uint4* d = reinterpret_cast<uint4*>(g_xprep) + (size_t)row * 8 + half * 4;
#pragma unroll
        for (int j = 0; j < 4; ++j)
            d[j] = make_uint4(hi[4*j], hi[4*j+1], hi[4*j+2], hi[4*j+3]);
    }
}

// ---------------------------------------------------------------------------
// Main HMMA pass. Each CTA: one strip (blockIdx.y), NBG consecutive n-blocks
// (blockIdx.x), A tile loaded once, B tiles double-buffered.
// do_store=0: exp-sums into g_partials. do_store=1: normalized float4 stores.
// ---------------------------------------------------------------------------
__global__ __launch_bounds__(256, 2)
void mma_pass_kernel(float* __restrict__ out, int do_store) {
    extern __shared__ uint32_t smem[];

    const int tid  = threadIdx.x;
    const int wid  = tid >> 5;
    const int lane = tid & 31;
    const int m0  = blockIdx.y * MT;
    const int nb0 = blockIdx.x * NBG;

    const uint32_t sA_a  = smem_u32(smem);
    const uint32_t sB0_a = sA_a + TILE_BYTES;

    // per-thread copy offsets (4 uint4 per tile per thread)
    uint32_t poff[4];
    int      pidx[4];
#pragma unroll
    for (int j = 0; j < 4; ++j) {
        int f = tid + 256 * j;
        pidx[j] = f;
        poff[j] = ((f >> 3) * PITCH + (f & 7) * 4) * 4;
    }

    // g0 = A + B(nb0), g1 = B(nb0+1)
    {
        const uint4* gA = reinterpret_cast<const uint4*>(g_xprep + (size_t)m0 * 32);
        const uint4* gB = reinterpret_cast<const uint4*>(g_wprep + (size_t)nb0 * NT * 32);
#pragma unroll
        for (int j = 0; j < 4; ++j) {
            cpa16(sA_a + poff[j], gA + pidx[j]);
            cpa16(sB0_a + poff[j], gB + pidx[j]);
        }
        asm volatile("cp.async.commit_group;" ::: "memory");
        const uint4* gB1 = reinterpret_cast<const uint4*>(g_wprep + (size_t)(nb0 + 1) * NT * 32);
#pragma unroll
        for (int j = 0; j < 4; ++j)
            cpa16(sB0_a + TILE_BYTES + poff[j], gB1 + pidx[j]);
        asm volatile("cp.async.commit_group;" ::: "memory");
    }

    // fragment lane constants
    const int wm = wid & 3;
    const int wn = wid >> 2;
    const int g  = lane >> 2;
    const int t  = lane & 3;
    const int jj = t >> 1;        // float4 pair index
    const int odd = t & 1;

    uint32_t aBase[2];
    {
        int arow = lane & 15;
        int ako  = (lane >> 4) * 16;
#pragma unroll
        for (int mi = 0; mi < 2; ++mi)
            aBase[mi] = sA_a + (uint32_t)(wm * 32 + mi * 16 + arow) * (PITCH * 4u) + ako;
    }
    const uint32_t bLane = (uint32_t)((lane & 7) + ((lane >> 4) & 1) * 8) * (PITCH * 4u)
                         + ((lane >> 3) & 1) * 16;

    for (int i = 0; i < NBG; ++i) {
        asm volatile("cp.async.wait_group 1;" ::: "memory");
        __syncthreads();

        const uint32_t sB_a = sB0_a + (uint32_t)(i & 1) * TILE_BYTES;
        const int nb = nb0 + i;
        const int n0 = nb * NT;

        uint32_t bBase[4];
#pragma unroll
        for (int np = 0; np < 4; ++np)
            bBase[np] = sB_a + (uint32_t)(wn * 64 + np * 16) * (PITCH * 4u) + bLane;

        float acc[2][8][4];
#pragma unroll
        for (int mi = 0; mi < 2; ++mi)
#pragma unroll
            for (int ni = 0; ni < 8; ++ni)
#pragma unroll
                for (int c = 0; c < 4; ++c) acc[mi][ni][c] = 0.0f;

#pragma unroll
        for (int kc = 0; kc < 4; ++kc) {
            const uint32_t ko = kc * 32u;
            uint32_t ah[2][4];
#pragma unroll
            for (int mi = 0; mi < 2; ++mi)
                ldsm4(ah[mi], aBase[mi] + ko);
#pragma unroll
            for (int np = 0; np < 4; ++np) {
                uint32_t b[4];
                ldsm4(b, bBase[np] + ko);
#pragma unroll
                for (int mi = 0; mi < 2; ++mi) {
                    mma_f16(acc[mi][2*np],     ah[mi], b[0], b[1]);
                    mma_f16(acc[mi][2*np + 1], ah[mi], b[2], b[3]);
                }
            }
        }

        // done reading buffer (i&1); prefetch B(i+2) into it, behind epilogue
        __syncthreads();
        if (i + 2 < NBG) {
            const uint4* gB = reinterpret_cast<const uint4*>(
                g_wprep + (size_t)(nb0 + i + 2) * NT * 32);
            const uint32_t dst = sB0_a + (uint32_t)(i & 1) * TILE_BYTES;
#pragma unroll
            for (int j = 0; j < 4; ++j)
                cpa16(dst + poff[j], gB + pidx[j]);
        }
        asm volatile("cp.async.commit_group;" ::: "memory");

        // ---- epilogue ----
        if (do_store) {
#pragma unroll
            for (int mi = 0; mi < 2; ++mi) {
                const int rg = m0 + wm * 32 + mi * 16 + g;
                const float inv0 = g_rowinv[rg];
                const float inv8 = g_rowinv[rg + 8];
                float* rowp = out + (size_t)(odd ? rg + 8 : rg) * D_OUT
                            + n0 + wn * 64 + jj * 4;
#pragma unroll
                for (int ni = 0; ni < 8; ++ni) {
                    float e0 = ex2(acc[mi][ni][0]) * inv0;
                    float e1 = ex2(acc[mi][ni][1]) * inv0;
                    float e2 = ex2(acc[mi][ni][2]) * inv8;
                    float e3 = ex2(acc[mi][ni][3]) * inv8;
                    // pair exchange: even lane gets odd's (e0,e1); odd gets even's (e2,e3)
                    float sv0 = odd ? e0 : e2;
                    float sv1 = odd ? e1 : e3;
                    float rv0 = __shfl_xor_sync(0xffffffffu, sv0, 1);
                    float rv1 = __shfl_xor_sync(0xffffffffu, sv1, 1);
                    float4 v = odd ? make_float4(rv0, rv1, e2, e3)
                                   : make_float4(e0, e1, rv0, rv1);
                    __stcs(reinterpret_cast<float4*>(rowp + ni * 8), v);
                }
            }
        } else {
#pragma unroll
            for (int mi = 0; mi < 2; ++mi) {
                const int rg = m0 + wm * 32 + mi * 16 + g;
                float s0 = 0.0f, s8 = 0.0f;
#pragma unroll
                for (int ni = 0; ni < 8; ++ni) {
                    float2 f01 = ex2_pair(acc[mi][ni][0], acc[mi][ni][1]);
                    float2 f23 = ex2_pair(acc[mi][ni][2], acc[mi][ni][3]);
                    s0 += f01.x + f01.y;
                    s8 += f23.x + f23.y;
                }
                s0 += __shfl_xor_sync(0xffffffffu, s0, 1);
                s0 += __shfl_xor_sync(0xffffffffu, s0, 2);
                s8 += __shfl_xor_sync(0xffffffffu, s8, 1);
                s8 += __shfl_xor_sync(0xffffffffu, s8, 2);
                if (t == 0) {
                    int pcol = nb * 2 + wn;
                    __stcs(&g_partials[(size_t)rg * NBLK2 + pcol], s0);
                    __stcs(&g_partials[(size_t)(rg + 8) * NBLK2 + pcol], s8);
                }
            }
        }
    }
}

// ---------------------------------------------------------------------------
__global__ __launch_bounds__(256) void rowinv_kernel() {
    int warp = threadIdx.x >> 5;
    int lane = threadIdx.x & 31;
    int row = blockIdx.x * 8 + warp;
    float s = 0.0f;
    for (int i = lane; i < NBLK2; i += 32) s += g_partials[(size_t)row * NBLK2 + i];
#pragma unroll
    for (int off = 16; off >= 1; off >>= 1)
        s += __shfl_xor_sync(0xffffffffu, s, off);
    if (lane == 0) g_rowinv[row] = 1.0f / s;
}

__global__ void tail_kernel(float* __restrict__ out, long long base, long long n) {
    long long i = (long long)blockIdx.x * 256 + threadIdx.x;
    if (i < n) out[base + i] = 0.0f;
}

extern "C" void kernel_launch(void* const* d_in, const int* in_sizes, int n_in,
                              void* d_out, int out_size) {
    const float* x = (const float*)d_in[0];
    const float* w = (const float*)d_in[1];
    float* out = (float*)d_out;

    const int smem_bytes = 3 * TILE_BYTES;   // 55296 (A + 2 B buffers)
    static int attr_set = 0;
    if (!attr_set) {
        cudaFuncSetAttribute(mma_pass_kernel,
                             cudaFuncAttributeMaxDynamicSharedMemorySize, smem_bytes);
        attr_set = 1;
    }

    prep_kernel<<<189, 256>>>(w, x);

    dim3 grid(NGX, MBLK);   // (25, 64) -> 1600 CTAs, 10 n-blocks each
    mma_pass_kernel<<<grid, 256, smem_bytes>>>(out, 0);
    rowinv_kernel<<<NROWS / 8, 256>>>();
    mma_pass_kernel<<<grid, 256, smem_bytes>>>(out, 1);

    long long n_main = (long long)NROWS * D_OUT;
    long long tail = (long long)out_size - n_main;
    if (tail > 0) {
        int blocks = (int)((tail + 255) / 256);
        tail_kernel<<<blocks, 256>>>(out, n_main, tail);
    }
}